// round 13
// baseline (speedup 1.0000x reference)
#include <cuda_runtime.h>
#include <math.h>

#define N_PTS 8192
#define KMASK 0xFFFFE000u
#define IDXMASK 8191u

#define TPT 16                        // targets per thread (register resident)
#define BT 512                        // threads per block -> 8192 targets/block
#define SRC_TILE 56                   // sources per block
#define NBLK 147                      // ceil(8192/56) -> ~1 CTA per SM
#define FB 128                        // epilogue blocks (small, co-residable)
#define FT 64                         // epilogue threads/block

// Stored value = ~packed_key with atomicMax; zero-init always loses
// (key <= 0xFF7FFFFF so ~key >= 0x00800000 > 0). Epilogue resets to 0.
__device__ unsigned g_rowmin[N_PTS];
__device__ unsigned g_colmin[N_PTS];
__device__ float g_part[FB][4];
__device__ unsigned g_done;           // finisher resets to 0 (replay-safe)

// ---- packed f32x2 helpers (Blackwell FFMA2/FADD2) -------------------------
__device__ __forceinline__ unsigned long long pk2(float lo, float hi) {
    unsigned long long d;
    asm("mov.b64 %0,{%1,%2};" : "=l"(d) : "f"(lo), "f"(hi));
    return d;
}
__device__ __forceinline__ unsigned long long add2(unsigned long long a, unsigned long long b) {
    unsigned long long d;
    asm("add.rn.f32x2 %0,%1,%2;" : "=l"(d) : "l"(a), "l"(b));
    return d;
}
__device__ __forceinline__ unsigned long long fma2(unsigned long long a, unsigned long long b, unsigned long long c) {
    unsigned long long d;
    asm("fma.rn.f32x2 %0,%1,%2,%3;" : "=l"(d) : "l"(a), "l"(b), "l"(c));
    return d;
}
__device__ __forceinline__ void upk(unsigned long long d, unsigned& lo, unsigned& hi) {
    asm("mov.b64 {%0,%1},%2;" : "=r"(lo), "=r"(hi) : "l"(d));
}

// rotation_6d -> R (row-major)
__device__ __forceinline__ void make_R(const float* __restrict__ r6, float R[9]) {
    float a1x = r6[0], a1y = r6[1], a1z = r6[2];
    float a2x = r6[3], a2y = r6[4], a2z = r6[5];
    float n1 = sqrtf(a1x*a1x + a1y*a1y + a1z*a1z);
    float b1x = a1x/n1, b1y = a1y/n1, b1z = a1z/n1;
    float dd = b1x*a2x + b1y*a2y + b1z*a2z;
    float c2x = a2x - dd*b1x, c2y = a2y - dd*b1y, c2z = a2z - dd*b1z;
    float n2 = sqrtf(c2x*c2x + c2y*c2y + c2z*c2z);
    float b2x = c2x/n2, b2y = c2y/n2, b2z = c2z/n2;
    R[0] = b1x; R[1] = b2x; R[2] = b1y*b2z - b1z*b2y;
    R[3] = b1y; R[4] = b2y; R[5] = b1z*b2x - b1x*b2z;
    R[6] = b1z; R[7] = b2z; R[8] = b1x*b2y - b1y*b2x;
}

// ---------------------------------------------------------------------------
// Kernel 1: pair pass, f32x2-packed, 147 blocks x 512 threads, occ 1.
// Each block: ALL 8192 targets in registers (16/thread), 56 sources streamed.
// Key: (bits(m)&KMASK)+idx via VIADDMIN; min(d2) == min(uint key) since m<0.
// PDL trigger fires EARLY (after tile load) so the epilogue's prologue can
// overlap the pair loop; griddepcontrol.wait in k_final gates correctness.
// ---------------------------------------------------------------------------
__global__ void __launch_bounds__(BT, 1) k_pairs(const float* __restrict__ sp,
                                                 const float* __restrict__ tp,
                                                 const float* __restrict__ tr,
                                                 const float* __restrict__ r6,
                                                 const float* __restrict__ sc) {
    const int tid = threadIdx.x;

    __shared__ ulonglong2 sS[SRC_TILE][2];  // [s][0]={x,y} [s][1]={z,w} splatted

    // --- source tile: transform raw sources (threads < slen) ---
    const int sbase = blockIdx.x * SRC_TILE;
    const int slen = min(SRC_TILE, N_PTS - sbase);
    if (tid < slen) {
        float R[9];
        make_R(r6, R);
        float t0 = tr[0], t1 = tr[1], t2 = tr[2];
        float s0 = sc[0], s1 = sc[1], s2 = sc[2];
        int i = sbase + tid;
        float px = sp[3*i+0] * s0, py = sp[3*i+1] * s1, pz = sp[3*i+2] * s2;
        float vx = R[0]*px + R[1]*py + R[2]*pz + t0;
        float vy = R[3]*px + R[4]*py + R[5]*pz + t1;
        float vz = R[6]*px + R[7]*py + R[8]*pz + t2;
        float hs = -0.5f * (vx*vx + vy*vy + vz*vz);
        sS[tid][0] = make_ulonglong2(pk2(vx, vx), pk2(vy, vy));
        sS[tid][1] = make_ulonglong2(pk2(vz, vz), pk2(hs, hs));
    }

    // --- target tile: 16 raw targets per thread (full 8192), ht inline ---
    unsigned long long Tx[TPT/2], Ty[TPT/2], Tz[TPT/2], Tw[TPT/2];
    unsigned ck[TPT];
    unsigned cu[TPT];
#pragma unroll
    for (int p = 0; p < TPT/2; p++) {
        int ia = tid + (2*p)   * BT;
        int ib = tid + (2*p+1) * BT;
        float ax = tp[3*ia+0], ay = tp[3*ia+1], az = tp[3*ia+2];
        float bx = tp[3*ib+0], by = tp[3*ib+1], bz = tp[3*ib+2];
        float ha = -0.5f*(ax*ax + ay*ay + az*az);
        float hb = -0.5f*(bx*bx + by*by + bz*bz);
        Tx[p] = pk2(ax, bx);
        Ty[p] = pk2(ay, by);
        Tz[p] = pk2(az, bz);
        Tw[p] = pk2(ha, hb);
    }
#pragma unroll
    for (int u = 0; u < TPT; u++) {
        ck[u] = 0xFFFFFFFFu;
        cu[u] = (unsigned)(tid + u * BT);
    }
    __syncthreads();

    // EARLY PDL trigger: dependent grid may start its pre-wait prologue now.
    asm volatile("griddepcontrol.launch_dependents;");

    for (int s = 0; s < slen; s++) {
        ulonglong2 a = sS[s][0];
        ulonglong2 b2v = sS[s][1];
        unsigned long long Sx = a.x, Sy = a.y, Sz = b2v.x, Sw = b2v.y;
        const unsigned skey = (unsigned)(sbase + s);
        unsigned rloc0 = 0xFFFFFFFFu, rloc1 = 0xFFFFFFFFu;   // split chains
#pragma unroll
        for (int p = 0; p < TPT/2; p++) {
            unsigned long long acc = add2(Tw[p], Sw);
            acc = fma2(Tx[p], Sx, acc);
            acc = fma2(Ty[p], Sy, acc);
            acc = fma2(Tz[p], Sz, acc);
            unsigned b0, b1;
            upk(acc, b0, b1);
            unsigned m0 = b0 & KMASK;
            unsigned m1 = b1 & KMASK;
            // masked|idx == masked+idx (low 13 bits of masked are 0)
            rloc0     = __viaddmin_u32(m0, cu[2*p],   rloc0);
            rloc1     = __viaddmin_u32(m1, cu[2*p+1], rloc1);
            ck[2*p]   = __viaddmin_u32(m0, skey, ck[2*p]);
            ck[2*p+1] = __viaddmin_u32(m1, skey, ck[2*p+1]);
        }
        unsigned rloc = umin(rloc0, rloc1);
        rloc = __reduce_min_sync(0xFFFFFFFFu, rloc);   // REDUX.SYNC.MIN
        if ((tid & 31) == 0) atomicMax(&g_rowmin[skey], ~rloc);
    }

#pragma unroll
    for (int u = 0; u < TPT; u++)
        atomicMax(&g_colmin[cu[u]], ~ck[u]);
}

// ---------------------------------------------------------------------------
// Kernel 2: exact epilogue + fused finish. 128 blocks x 64 threads — small
// enough to co-reside with k_pairs CTAs so the prologue overlaps the pair
// loop. griddepcontrol.wait gates all result reads.
// ---------------------------------------------------------------------------
__global__ void __launch_bounds__(FT) k_final(
                        const float* __restrict__ sp, const float* __restrict__ tp,
                        const float* __restrict__ sn, const float* __restrict__ tn,
                        const float* __restrict__ tr, const float* __restrict__ r6,
                        const float* __restrict__ sc, float* __restrict__ out) {
    const int tid = threadIdx.x;
    const int i = blockIdx.x * FT + tid;
    const float EPS = 1e-6f;

    // ---- result-independent prologue (overlaps k_pairs) ----
    float R[9];
    make_R(r6, R);
    const float t0 = tr[0], t1 = tr[1], t2 = tr[2];
    const float s0 = sc[0], s1 = sc[1], s2 = sc[2];

    float six, siy, siz, nix, niy, niz, nin;
    {
        float px = sp[3*i+0]*s0, py = sp[3*i+1]*s1, pz = sp[3*i+2]*s2;
        six = R[0]*px + R[1]*py + R[2]*pz + t0;
        siy = R[3]*px + R[4]*py + R[5]*pz + t1;
        siz = R[6]*px + R[7]*py + R[8]*pz + t2;
        float nx = sn[3*i+0], ny = sn[3*i+1], nz = sn[3*i+2];
        nix = R[0]*nx + R[1]*ny + R[2]*nz;
        niy = R[3]*nx + R[4]*ny + R[5]*nz;
        niz = R[6]*nx + R[7]*ny + R[8]*nz;
        nin = sqrtf(nix*nix + niy*niy + niz*niz);
    }
    float tix = tp[3*i+0], tiy = tp[3*i+1], tiz = tp[3*i+2];
    float tnx = tn[3*i+0], tny = tn[3*i+1], tnz = tn[3*i+2];

    // ---- wait for k_pairs results (full primary-grid completion) ----
    asm volatile("griddepcontrol.wait;");

    unsigned rv = g_rowmin[i];
    unsigned cv = g_colmin[i];
    g_rowmin[i] = 0u;   // reset for next replay (single reader each)
    g_colmin[i] = 0u;
    int jr = (int)((~rv) & IDXMASK);
    int jc = (int)((~cv) & IDXMASK);

    float v0, v1, v2, v3;
    {
        // source i -> target jr
        float tx = tp[3*jr+0], ty = tp[3*jr+1], tz = tp[3*jr+2];
        float ns  = six*six + siy*siy + siz*siz;
        float nt2 = tx*tx + ty*ty + tz*tz;
        float dp  = six*tx + siy*ty + siz*tz;
        v0 = fmaxf(ns + nt2 - 2.f*dp, 0.f);

        float ax = tn[3*jr+0], ay = tn[3*jr+1], az = tn[3*jr+2];
        float an = sqrtf(ax*ax + ay*ay + az*az);
        float cs = (nix*ax + niy*ay + niz*az) /
                   (fmaxf(nin, EPS) * fmaxf(an, EPS));
        v2 = 1.f - fabsf(cs);
    }
    {
        // target i -> source jc
        float px = sp[3*jc+0]*s0, py = sp[3*jc+1]*s1, pz = sp[3*jc+2]*s2;
        float sx = R[0]*px + R[1]*py + R[2]*pz + t0;
        float sy = R[3]*px + R[4]*py + R[5]*pz + t1;
        float sz = R[6]*px + R[7]*py + R[8]*pz + t2;
        float ns  = sx*sx + sy*sy + sz*sz;
        float nt2 = tix*tix + tiy*tiy + tiz*tiz;
        float dp  = sx*tix + sy*tiy + sz*tiz;
        v1 = fmaxf(ns + nt2 - 2.f*dp, 0.f);

        float an = sqrtf(tnx*tnx + tny*tny + tnz*tnz);
        float nx = sn[3*jc+0], ny = sn[3*jc+1], nz = sn[3*jc+2];
        float wx = R[0]*nx + R[1]*ny + R[2]*nz;
        float wy = R[3]*nx + R[4]*ny + R[5]*nz;
        float wz = R[6]*nx + R[7]*ny + R[8]*nz;
        float wn = sqrtf(wx*wx + wy*wy + wz*wz);
        float cs = (tnx*wx + tny*wy + tnz*wz) /
                   (fmaxf(an, EPS) * fmaxf(wn, EPS));
        v3 = 1.f - fabsf(cs);
    }

    // deterministic block reduction (2 warps)
    float v[4] = {v0, v1, v2, v3};
#pragma unroll
    for (int k = 0; k < 4; k++)
#pragma unroll
        for (int off = 16; off; off >>= 1)
            v[k] += __shfl_xor_sync(0xFFFFFFFFu, v[k], off);

    __shared__ float sh[2][4];
    __shared__ bool s_last;
    const int warp = tid >> 5;
    if ((tid & 31) == 0) {
        sh[warp][0] = v[0]; sh[warp][1] = v[1];
        sh[warp][2] = v[2]; sh[warp][3] = v[3];
    }
    __syncthreads();
    if (tid == 0) {
#pragma unroll
        for (int k = 0; k < 4; k++)
            g_part[blockIdx.x][k] = sh[0][k] + sh[1][k];
        __threadfence();
        s_last = (atomicAdd(&g_done, 1u) == (unsigned)(FB - 1));
    }
    __syncthreads();

    if (s_last && tid < 32) {
        __threadfence();
        float w[4];
#pragma unroll
        for (int k = 0; k < 4; k++)
            w[k] = g_part[tid][k] + g_part[tid + 32][k]
                 + g_part[tid + 64][k] + g_part[tid + 96][k];
#pragma unroll
        for (int k = 0; k < 4; k++)
#pragma unroll
            for (int off = 16; off; off >>= 1)
                w[k] += __shfl_xor_sync(0xFFFFFFFFu, w[k], off);
        if (tid == 0) {
            const float invN = 1.0f / (float)N_PTS;
            out[0] = w[0]*invN + w[1]*invN + 0.1f*(w[2]*invN + w[3]*invN);
            g_done = 0u;   // reset for next replay
        }
    }
}

// ---------------------------------------------------------------------------
extern "C" void kernel_launch(void* const* d_in, const int* in_sizes, int n_in,
                              void* d_out, int out_size) {
    const float* sp = (const float*)d_in[0];
    const float* tp = (const float*)d_in[1];
    const float* sn = (const float*)d_in[2];
    const float* tn = (const float*)d_in[3];
    const float* tr = (const float*)d_in[4];
    const float* r6 = (const float*)d_in[5];
    const float* sc = (const float*)d_in[6];
    float* out = (float*)d_out;

    k_pairs<<<NBLK, BT>>>(sp, tp, tr, r6, sc);

    // PDL launch of the epilogue: prologue overlaps k_pairs execution
    cudaLaunchConfig_t cfg = {};
    cfg.gridDim = dim3(FB);
    cfg.blockDim = dim3(FT);
    cfg.dynamicSmemBytes = 0;
    cfg.stream = 0;
    cudaLaunchAttribute attrs[1];
    attrs[0].id = cudaLaunchAttributeProgrammaticStreamSerialization;
    attrs[0].val.programmaticStreamSerializationAllowed = 1;
    cfg.attrs = attrs;
    cfg.numAttrs = 1;
    cudaLaunchKernelEx(&cfg, k_final, sp, tp, sn, tn, tr, r6, sc, (float*)out);
}

// round 14
// speedup vs baseline: 1.1146x; 1.1146x over previous
#include <cuda_runtime.h>
#include <math.h>

#define N_PTS 8192
#define KMASK 0xFFFFE000u
#define IDXMASK 8191u

#define TPT 16                        // targets per thread (register resident)
#define BT 512                        // threads per block -> 8192 targets/block
#define SRC_TILE 56                   // sources per block (compile-time loop)
#define NBLK 147                      // 147*56 = 8232; tail clamps to 8191 (idempotent)
#define FB 64                         // epilogue blocks
#define FT 128                        // epilogue threads/block

// Stored value = ~packed_key with atomicMax; zero-init always loses
// (key <= 0xFF7FFFFF so ~key >= 0x00800000 > 0). Epilogue resets to 0.
__device__ unsigned g_rowmin[N_PTS];
__device__ unsigned g_colmin[N_PTS];
__device__ float g_part[FB][4];
__device__ unsigned g_done;           // finisher resets to 0 (replay-safe)

// ---- packed f32x2 helpers (Blackwell FFMA2/FADD2) -------------------------
__device__ __forceinline__ unsigned long long pk2(float lo, float hi) {
    unsigned long long d;
    asm("mov.b64 %0,{%1,%2};" : "=l"(d) : "f"(lo), "f"(hi));
    return d;
}
__device__ __forceinline__ unsigned long long add2(unsigned long long a, unsigned long long b) {
    unsigned long long d;
    asm("add.rn.f32x2 %0,%1,%2;" : "=l"(d) : "l"(a), "l"(b));
    return d;
}
__device__ __forceinline__ unsigned long long fma2(unsigned long long a, unsigned long long b, unsigned long long c) {
    unsigned long long d;
    asm("fma.rn.f32x2 %0,%1,%2,%3;" : "=l"(d) : "l"(a), "l"(b), "l"(c));
    return d;
}
__device__ __forceinline__ void upk(unsigned long long d, unsigned& lo, unsigned& hi) {
    asm("mov.b64 {%0,%1},%2;" : "=r"(lo), "=r"(hi) : "l"(d));
}

// rotation_6d -> R (row-major)
__device__ __forceinline__ void make_R(const float* __restrict__ r6, float R[9]) {
    float a1x = r6[0], a1y = r6[1], a1z = r6[2];
    float a2x = r6[3], a2y = r6[4], a2z = r6[5];
    float n1 = sqrtf(a1x*a1x + a1y*a1y + a1z*a1z);
    float b1x = a1x/n1, b1y = a1y/n1, b1z = a1z/n1;
    float dd = b1x*a2x + b1y*a2y + b1z*a2z;
    float c2x = a2x - dd*b1x, c2y = a2y - dd*b1y, c2z = a2z - dd*b1z;
    float n2 = sqrtf(c2x*c2x + c2y*c2y + c2z*c2z);
    float b2x = c2x/n2, b2y = c2y/n2, b2z = c2z/n2;
    R[0] = b1x; R[1] = b2x; R[2] = b1y*b2z - b1z*b2y;
    R[3] = b1y; R[4] = b2y; R[5] = b1z*b2x - b1x*b2z;
    R[6] = b1z; R[7] = b2z; R[8] = b1x*b2y - b1y*b2x;
}

// ---------------------------------------------------------------------------
// Kernel 1: pair pass, f32x2-packed, 147 blocks x 512 threads, occ 1.
// Each block: ALL 8192 targets in registers (16/thread), 56 sources streamed.
// Rowmin key = (bits(m)&KMASK) + u*BT (imm) accumulated per chain; the
// thread-constant tid is added ONCE after the chain merge (no carry: low-13
// field = u*512 + tid <= 8191). Colmin key = (bits(m)&KMASK) + skey.
// Last block clamps overhanging source indices to 8191 (idempotent dups).
// ---------------------------------------------------------------------------
__global__ void __launch_bounds__(BT, 1) k_pairs(const float* __restrict__ sp,
                                                 const float* __restrict__ tp,
                                                 const float* __restrict__ tr,
                                                 const float* __restrict__ r6,
                                                 const float* __restrict__ sc) {
    const int tid = threadIdx.x;

    __shared__ ulonglong2 sS[SRC_TILE][2];  // [s][0]={x,y} [s][1]={z,w} splatted

    // --- source tile: transform raw sources (clamped index in last block) ---
    const int sbase = blockIdx.x * SRC_TILE;
    if (tid < SRC_TILE) {
        float R[9];
        make_R(r6, R);
        float t0 = tr[0], t1 = tr[1], t2 = tr[2];
        float s0 = sc[0], s1 = sc[1], s2 = sc[2];
        int i = min(sbase + tid, N_PTS - 1);     // clamp: duplicate of 8191 ok
        float px = sp[3*i+0] * s0, py = sp[3*i+1] * s1, pz = sp[3*i+2] * s2;
        float vx = R[0]*px + R[1]*py + R[2]*pz + t0;
        float vy = R[3]*px + R[4]*py + R[5]*pz + t1;
        float vz = R[6]*px + R[7]*py + R[8]*pz + t2;
        float hs = -0.5f * (vx*vx + vy*vy + vz*vz);
        sS[tid][0] = make_ulonglong2(pk2(vx, vx), pk2(vy, vy));
        sS[tid][1] = make_ulonglong2(pk2(vz, vz), pk2(hs, hs));
    }

    // --- target tile: 16 raw targets per thread (full 8192), ht inline ---
    unsigned long long Tx[TPT/2], Ty[TPT/2], Tz[TPT/2], Tw[TPT/2];
    unsigned ck[TPT];
#pragma unroll
    for (int p = 0; p < TPT/2; p++) {
        int ia = tid + (2*p)   * BT;
        int ib = tid + (2*p+1) * BT;
        float ax = tp[3*ia+0], ay = tp[3*ia+1], az = tp[3*ia+2];
        float bx = tp[3*ib+0], by = tp[3*ib+1], bz = tp[3*ib+2];
        float ha = -0.5f*(ax*ax + ay*ay + az*az);
        float hb = -0.5f*(bx*bx + by*by + bz*bz);
        Tx[p] = pk2(ax, bx);
        Ty[p] = pk2(ay, by);
        Tz[p] = pk2(az, bz);
        Tw[p] = pk2(ha, hb);
    }
#pragma unroll
    for (int u = 0; u < TPT; u++)
        ck[u] = 0xFFFFFFFFu;
    __syncthreads();

    for (int s = 0; s < SRC_TILE; s++) {
        ulonglong2 a = sS[s][0];
        ulonglong2 b2v = sS[s][1];
        unsigned long long Sx = a.x, Sy = a.y, Sz = b2v.x, Sw = b2v.y;
        const unsigned skey = (unsigned)min(sbase + s, N_PTS - 1);
        unsigned rloc0 = 0xFFFFFFFFu, rloc1 = 0xFFFFFFFFu;   // split chains
#pragma unroll
        for (int p = 0; p < TPT/2; p++) {
            unsigned long long acc = add2(Tw[p], Sw);
            acc = fma2(Tx[p], Sx, acc);
            acc = fma2(Ty[p], Sy, acc);
            acc = fma2(Tz[p], Sz, acc);
            unsigned b0, b1;
            upk(acc, b0, b1);
            unsigned m0 = b0 & KMASK;
            unsigned m1 = b1 & KMASK;
            // row keys: u*BT is an immediate; tid added after the chain merge
            rloc0     = __viaddmin_u32(m0, (unsigned)((2*p)   * BT), rloc0);
            rloc1     = __viaddmin_u32(m1, (unsigned)((2*p+1) * BT), rloc1);
            // col keys: masked|skey == masked+skey (low 13 bits of masked are 0)
            ck[2*p]   = __viaddmin_u32(m0, skey, ck[2*p]);
            ck[2*p+1] = __viaddmin_u32(m1, skey, ck[2*p+1]);
        }
        unsigned rloc = umin(rloc0, rloc1) + (unsigned)tid;  // finish row key
        rloc = __reduce_min_sync(0xFFFFFFFFu, rloc);         // REDUX.SYNC.MIN
        if ((tid & 31) == 0) atomicMax(&g_rowmin[skey], ~rloc);
    }

#pragma unroll
    for (int u = 0; u < TPT; u++)
        atomicMax(&g_colmin[tid + u * BT], ~ck[u]);

    // PDL: allow the epilogue kernel to start its prologue now
    asm volatile("griddepcontrol.launch_dependents;");
}

// ---------------------------------------------------------------------------
// Kernel 2: exact epilogue + fused finish. PDL: result-independent prologue
// runs before griddepcontrol.wait (overlaps with k_pairs tail).
// ---------------------------------------------------------------------------
__global__ void k_final(const float* __restrict__ sp, const float* __restrict__ tp,
                        const float* __restrict__ sn, const float* __restrict__ tn,
                        const float* __restrict__ tr, const float* __restrict__ r6,
                        const float* __restrict__ sc, float* __restrict__ out) {
    const int tid = threadIdx.x;
    const int i = blockIdx.x * FT + tid;
    const float EPS = 1e-6f;

    // ---- result-independent prologue ----
    float R[9];
    make_R(r6, R);
    const float t0 = tr[0], t1 = tr[1], t2 = tr[2];
    const float s0 = sc[0], s1 = sc[1], s2 = sc[2];

    float six, siy, siz, nix, niy, niz, nin;
    {
        float px = sp[3*i+0]*s0, py = sp[3*i+1]*s1, pz = sp[3*i+2]*s2;
        six = R[0]*px + R[1]*py + R[2]*pz + t0;
        siy = R[3]*px + R[4]*py + R[5]*pz + t1;
        siz = R[6]*px + R[7]*py + R[8]*pz + t2;
        float nx = sn[3*i+0], ny = sn[3*i+1], nz = sn[3*i+2];
        nix = R[0]*nx + R[1]*ny + R[2]*nz;
        niy = R[3]*nx + R[4]*ny + R[5]*nz;
        niz = R[6]*nx + R[7]*ny + R[8]*nz;
        nin = sqrtf(nix*nix + niy*niy + niz*niz);
    }
    float tix = tp[3*i+0], tiy = tp[3*i+1], tiz = tp[3*i+2];
    float tnx = tn[3*i+0], tny = tn[3*i+1], tnz = tn[3*i+2];

    // ---- wait for k_pairs results ----
    asm volatile("griddepcontrol.wait;");

    unsigned rv = g_rowmin[i];
    unsigned cv = g_colmin[i];
    g_rowmin[i] = 0u;   // reset for next replay (single reader each)
    g_colmin[i] = 0u;
    int jr = (int)((~rv) & IDXMASK);
    int jc = (int)((~cv) & IDXMASK);

    float v0, v1, v2, v3;
    {
        // source i -> target jr
        float tx = tp[3*jr+0], ty = tp[3*jr+1], tz = tp[3*jr+2];
        float ns  = six*six + siy*siy + siz*siz;
        float nt2 = tx*tx + ty*ty + tz*tz;
        float dp  = six*tx + siy*ty + siz*tz;
        v0 = fmaxf(ns + nt2 - 2.f*dp, 0.f);

        float ax = tn[3*jr+0], ay = tn[3*jr+1], az = tn[3*jr+2];
        float an = sqrtf(ax*ax + ay*ay + az*az);
        float cs = (nix*ax + niy*ay + niz*az) /
                   (fmaxf(nin, EPS) * fmaxf(an, EPS));
        v2 = 1.f - fabsf(cs);
    }
    {
        // target i -> source jc
        float px = sp[3*jc+0]*s0, py = sp[3*jc+1]*s1, pz = sp[3*jc+2]*s2;
        float sx = R[0]*px + R[1]*py + R[2]*pz + t0;
        float sy = R[3]*px + R[4]*py + R[5]*pz + t1;
        float sz = R[6]*px + R[7]*py + R[8]*pz + t2;
        float ns  = sx*sx + sy*sy + sz*sz;
        float nt2 = tix*tix + tiy*tiy + tiz*tiz;
        float dp  = sx*tix + sy*tiy + sz*tiz;
        v1 = fmaxf(ns + nt2 - 2.f*dp, 0.f);

        float an = sqrtf(tnx*tnx + tny*tny + tnz*tnz);
        float nx = sn[3*jc+0], ny = sn[3*jc+1], nz = sn[3*jc+2];
        float wx = R[0]*nx + R[1]*ny + R[2]*nz;
        float wy = R[3]*nx + R[4]*ny + R[5]*nz;
        float wz = R[6]*nx + R[7]*ny + R[8]*nz;
        float wn = sqrtf(wx*wx + wy*wy + wz*wz);
        float cs = (tnx*wx + tny*wy + tnz*wz) /
                   (fmaxf(an, EPS) * fmaxf(wn, EPS));
        v3 = 1.f - fabsf(cs);
    }

    // deterministic block reduction (4 warps)
    float v[4] = {v0, v1, v2, v3};
#pragma unroll
    for (int k = 0; k < 4; k++)
#pragma unroll
        for (int off = 16; off; off >>= 1)
            v[k] += __shfl_xor_sync(0xFFFFFFFFu, v[k], off);

    __shared__ float sh[4][4];
    __shared__ bool s_last;
    const int warp = tid >> 5;
    if ((tid & 31) == 0) {
        sh[warp][0] = v[0]; sh[warp][1] = v[1];
        sh[warp][2] = v[2]; sh[warp][3] = v[3];
    }
    __syncthreads();
    if (tid == 0) {
#pragma unroll
        for (int k = 0; k < 4; k++) {
            float p = 0.f;
#pragma unroll
            for (int w = 0; w < 4; w++) p += sh[w][k];
            g_part[blockIdx.x][k] = p;
        }
        __threadfence();
        s_last = (atomicAdd(&g_done, 1u) == (unsigned)(FB - 1));
    }
    __syncthreads();

    if (s_last && tid < 32) {
        __threadfence();
        float w[4];
#pragma unroll
        for (int k = 0; k < 4; k++)
            w[k] = g_part[tid][k] + g_part[tid + 32][k];
#pragma unroll
        for (int k = 0; k < 4; k++)
#pragma unroll
            for (int off = 16; off; off >>= 1)
                w[k] += __shfl_xor_sync(0xFFFFFFFFu, w[k], off);
        if (tid == 0) {
            const float invN = 1.0f / (float)N_PTS;
            out[0] = w[0]*invN + w[1]*invN + 0.1f*(w[2]*invN + w[3]*invN);
            g_done = 0u;   // reset for next replay
        }
    }
}

// ---------------------------------------------------------------------------
extern "C" void kernel_launch(void* const* d_in, const int* in_sizes, int n_in,
                              void* d_out, int out_size) {
    const float* sp = (const float*)d_in[0];
    const float* tp = (const float*)d_in[1];
    const float* sn = (const float*)d_in[2];
    const float* tn = (const float*)d_in[3];
    const float* tr = (const float*)d_in[4];
    const float* r6 = (const float*)d_in[5];
    const float* sc = (const float*)d_in[6];
    float* out = (float*)d_out;

    k_pairs<<<NBLK, BT>>>(sp, tp, tr, r6, sc);

    // PDL launch of the epilogue: overlaps its prologue with k_pairs tail
    cudaLaunchConfig_t cfg = {};
    cfg.gridDim = dim3(FB);
    cfg.blockDim = dim3(FT);
    cfg.dynamicSmemBytes = 0;
    cfg.stream = 0;
    cudaLaunchAttribute attrs[1];
    attrs[0].id = cudaLaunchAttributeProgrammaticStreamSerialization;
    attrs[0].val.programmaticStreamSerializationAllowed = 1;
    cfg.attrs = attrs;
    cfg.numAttrs = 1;
    cudaLaunchKernelEx(&cfg, k_final, sp, tp, sn, tn, tr, r6, sc, (float*)out);
}

// round 15
// speedup vs baseline: 1.2796x; 1.1480x over previous
#include <cuda_runtime.h>
#include <math.h>

#define N_PTS 8192
#define KMASK 0xFFFFE000u
#define IDXMASK 8191u

#define TPT 16                        // targets per thread (register resident)
#define BT 512                        // threads per block -> 8192 targets/block
#define NWARP (BT/32)                 // 16
#define SRC_TILE 56                   // sources per block (compile-time loop)
#define NBLK 147                      // 147*56 = 8232; tail clamps to 8191 (idempotent)
#define FB 64                         // epilogue blocks
#define FT 128                        // epilogue threads/block

// g_rowmin: plain-stored packed key (block-local row min is globally final).
// g_colmin: ~packed_key accumulated with atomicMax; zero-init always loses
// (key <= 0xFF7FFFFF so ~key >= 0x00800000 > 0). Epilogue resets colmin to 0.
__device__ unsigned g_rowmin[N_PTS];
__device__ unsigned g_colmin[N_PTS];
__device__ float g_part[FB][4];
__device__ unsigned g_done;           // finisher resets to 0 (replay-safe)

// ---- packed f32x2 helpers (Blackwell FFMA2/FADD2) -------------------------
__device__ __forceinline__ unsigned long long pk2(float lo, float hi) {
    unsigned long long d;
    asm("mov.b64 %0,{%1,%2};" : "=l"(d) : "f"(lo), "f"(hi));
    return d;
}
__device__ __forceinline__ unsigned long long add2(unsigned long long a, unsigned long long b) {
    unsigned long long d;
    asm("add.rn.f32x2 %0,%1,%2;" : "=l"(d) : "l"(a), "l"(b));
    return d;
}
__device__ __forceinline__ unsigned long long fma2(unsigned long long a, unsigned long long b, unsigned long long c) {
    unsigned long long d;
    asm("fma.rn.f32x2 %0,%1,%2,%3;" : "=l"(d) : "l"(a), "l"(b), "l"(c));
    return d;
}
__device__ __forceinline__ void upk(unsigned long long d, unsigned& lo, unsigned& hi) {
    asm("mov.b64 {%0,%1},%2;" : "=r"(lo), "=r"(hi) : "l"(d));
}

// rotation_6d -> R (row-major)
__device__ __forceinline__ void make_R(const float* __restrict__ r6, float R[9]) {
    float a1x = r6[0], a1y = r6[1], a1z = r6[2];
    float a2x = r6[3], a2y = r6[4], a2z = r6[5];
    float n1 = sqrtf(a1x*a1x + a1y*a1y + a1z*a1z);
    float b1x = a1x/n1, b1y = a1y/n1, b1z = a1z/n1;
    float dd = b1x*a2x + b1y*a2y + b1z*a2z;
    float c2x = a2x - dd*b1x, c2y = a2y - dd*b1y, c2z = a2z - dd*b1z;
    float n2 = sqrtf(c2x*c2x + c2y*c2y + c2z*c2z);
    float b2x = c2x/n2, b2y = c2y/n2, b2z = c2z/n2;
    R[0] = b1x; R[1] = b2x; R[2] = b1y*b2z - b1z*b2y;
    R[3] = b1y; R[4] = b2y; R[5] = b1z*b2x - b1x*b2z;
    R[6] = b1z; R[7] = b2z; R[8] = b1x*b2y - b1y*b2x;
}

// ---------------------------------------------------------------------------
// Kernel 1: pair pass, f32x2-packed, 147 blocks x 512 threads, occ 1.
// Each block: ALL 8192 targets in registers (16/thread), 56 sources streamed.
// Row minimum is block-final (all targets present): per-warp REDUX -> STS ->
// block-end reduce -> plain STG (no atomics). Colmin via atomicMax(~key).
// Rowmin key = (bits(m)&KMASK) + u*BT (imm) per chain; thread-constant tid
// added once after chain merge (no carry: u*512 + tid <= 8191).
// ---------------------------------------------------------------------------
__global__ void __launch_bounds__(BT, 1) k_pairs(const float* __restrict__ sp,
                                                 const float* __restrict__ tp,
                                                 const float* __restrict__ tr,
                                                 const float* __restrict__ r6,
                                                 const float* __restrict__ sc) {
    const int tid = threadIdx.x;
    const int warp = tid >> 5;

    __shared__ ulonglong2 sS[SRC_TILE][2];       // [s][0]={x,y} [s][1]={z,w}
    __shared__ unsigned sWmin[SRC_TILE][NWARP];  // per-warp row mins

    // --- source tile: transform raw sources (clamped index in last block) ---
    const int sbase = blockIdx.x * SRC_TILE;
    if (tid < SRC_TILE) {
        float R[9];
        make_R(r6, R);
        float t0 = tr[0], t1 = tr[1], t2 = tr[2];
        float s0 = sc[0], s1 = sc[1], s2 = sc[2];
        int i = min(sbase + tid, N_PTS - 1);     // clamp: duplicate of 8191 ok
        float px = sp[3*i+0] * s0, py = sp[3*i+1] * s1, pz = sp[3*i+2] * s2;
        float vx = R[0]*px + R[1]*py + R[2]*pz + t0;
        float vy = R[3]*px + R[4]*py + R[5]*pz + t1;
        float vz = R[6]*px + R[7]*py + R[8]*pz + t2;
        float hs = -0.5f * (vx*vx + vy*vy + vz*vz);
        sS[tid][0] = make_ulonglong2(pk2(vx, vx), pk2(vy, vy));
        sS[tid][1] = make_ulonglong2(pk2(vz, vz), pk2(hs, hs));
    }

    // --- target tile: 16 raw targets per thread (full 8192), ht inline ---
    unsigned long long Tx[TPT/2], Ty[TPT/2], Tz[TPT/2], Tw[TPT/2];
    unsigned ck[TPT];
#pragma unroll
    for (int p = 0; p < TPT/2; p++) {
        int ia = tid + (2*p)   * BT;
        int ib = tid + (2*p+1) * BT;
        float ax = tp[3*ia+0], ay = tp[3*ia+1], az = tp[3*ia+2];
        float bx = tp[3*ib+0], by = tp[3*ib+1], bz = tp[3*ib+2];
        float ha = -0.5f*(ax*ax + ay*ay + az*az);
        float hb = -0.5f*(bx*bx + by*by + bz*bz);
        Tx[p] = pk2(ax, bx);
        Ty[p] = pk2(ay, by);
        Tz[p] = pk2(az, bz);
        Tw[p] = pk2(ha, hb);
    }
#pragma unroll
    for (int u = 0; u < TPT; u++)
        ck[u] = 0xFFFFFFFFu;
    __syncthreads();

    for (int s = 0; s < SRC_TILE; s++) {
        ulonglong2 a = sS[s][0];
        ulonglong2 b2v = sS[s][1];
        unsigned long long Sx = a.x, Sy = a.y, Sz = b2v.x, Sw = b2v.y;
        const unsigned skey = (unsigned)min(sbase + s, N_PTS - 1);
        unsigned rloc0 = 0xFFFFFFFFu, rloc1 = 0xFFFFFFFFu;   // split chains
#pragma unroll
        for (int p = 0; p < TPT/2; p++) {
            unsigned long long acc = add2(Tw[p], Sw);
            acc = fma2(Tx[p], Sx, acc);
            acc = fma2(Ty[p], Sy, acc);
            acc = fma2(Tz[p], Sz, acc);
            unsigned b0, b1;
            upk(acc, b0, b1);
            unsigned m0 = b0 & KMASK;
            unsigned m1 = b1 & KMASK;
            // row keys: u*BT is an immediate; tid added after the chain merge
            rloc0     = __viaddmin_u32(m0, (unsigned)((2*p)   * BT), rloc0);
            rloc1     = __viaddmin_u32(m1, (unsigned)((2*p+1) * BT), rloc1);
            // col keys: masked|skey == masked+skey (low 13 bits of masked are 0)
            ck[2*p]   = __viaddmin_u32(m0, skey, ck[2*p]);
            ck[2*p+1] = __viaddmin_u32(m1, skey, ck[2*p+1]);
        }
        unsigned rloc = umin(rloc0, rloc1) + (unsigned)tid;  // finish row key
        rloc = __reduce_min_sync(0xFFFFFFFFu, rloc);         // REDUX.SYNC.MIN
        if ((tid & 31) == 0) sWmin[s][warp] = rloc;          // plain STS
    }

    // colmin flush (cross-block accumulation still needs atomics)
#pragma unroll
    for (int u = 0; u < TPT; u++)
        atomicMax(&g_colmin[tid + u * BT], ~ck[u]);

    // rowmin block-final reduce + plain store (no atomics)
    __syncthreads();
    if (tid < SRC_TILE) {
        unsigned v = sWmin[tid][0];
#pragma unroll
        for (int w = 1; w < NWARP; w++)
            v = umin(v, sWmin[tid][w]);
        g_rowmin[min(sbase + tid, N_PTS - 1)] = v;   // duplicates store same value
    }

    // PDL: allow the epilogue kernel to start its prologue now
    asm volatile("griddepcontrol.launch_dependents;");
}

// ---------------------------------------------------------------------------
// Kernel 2: exact epilogue + fused finish. PDL: result-independent prologue
// runs before griddepcontrol.wait (overlaps with k_pairs tail).
// ---------------------------------------------------------------------------
__global__ void k_final(const float* __restrict__ sp, const float* __restrict__ tp,
                        const float* __restrict__ sn, const float* __restrict__ tn,
                        const float* __restrict__ tr, const float* __restrict__ r6,
                        const float* __restrict__ sc, float* __restrict__ out) {
    const int tid = threadIdx.x;
    const int i = blockIdx.x * FT + tid;
    const float EPS = 1e-6f;

    // ---- result-independent prologue ----
    float R[9];
    make_R(r6, R);
    const float t0 = tr[0], t1 = tr[1], t2 = tr[2];
    const float s0 = sc[0], s1 = sc[1], s2 = sc[2];

    float six, siy, siz, nix, niy, niz, nin;
    {
        float px = sp[3*i+0]*s0, py = sp[3*i+1]*s1, pz = sp[3*i+2]*s2;
        six = R[0]*px + R[1]*py + R[2]*pz + t0;
        siy = R[3]*px + R[4]*py + R[5]*pz + t1;
        siz = R[6]*px + R[7]*py + R[8]*pz + t2;
        float nx = sn[3*i+0], ny = sn[3*i+1], nz = sn[3*i+2];
        nix = R[0]*nx + R[1]*ny + R[2]*nz;
        niy = R[3]*nx + R[4]*ny + R[5]*nz;
        niz = R[6]*nx + R[7]*ny + R[8]*nz;
        nin = sqrtf(nix*nix + niy*niy + niz*niz);
    }
    float tix = tp[3*i+0], tiy = tp[3*i+1], tiz = tp[3*i+2];
    float tnx = tn[3*i+0], tny = tn[3*i+1], tnz = tn[3*i+2];

    // ---- wait for k_pairs results ----
    asm volatile("griddepcontrol.wait;");

    unsigned rv = g_rowmin[i];      // plain-stored key
    unsigned cv = g_colmin[i];
    g_colmin[i] = 0u;               // reset for next replay (single reader)
    int jr = (int)(rv & IDXMASK);
    int jc = (int)((~cv) & IDXMASK);

    float v0, v1, v2, v3;
    {
        // source i -> target jr
        float tx = tp[3*jr+0], ty = tp[3*jr+1], tz = tp[3*jr+2];
        float ns  = six*six + siy*siy + siz*siz;
        float nt2 = tx*tx + ty*ty + tz*tz;
        float dp  = six*tx + siy*ty + siz*tz;
        v0 = fmaxf(ns + nt2 - 2.f*dp, 0.f);

        float ax = tn[3*jr+0], ay = tn[3*jr+1], az = tn[3*jr+2];
        float an = sqrtf(ax*ax + ay*ay + az*az);
        float cs = (nix*ax + niy*ay + niz*az) /
                   (fmaxf(nin, EPS) * fmaxf(an, EPS));
        v2 = 1.f - fabsf(cs);
    }
    {
        // target i -> source jc
        float px = sp[3*jc+0]*s0, py = sp[3*jc+1]*s1, pz = sp[3*jc+2]*s2;
        float sx = R[0]*px + R[1]*py + R[2]*pz + t0;
        float sy = R[3]*px + R[4]*py + R[5]*pz + t1;
        float sz = R[6]*px + R[7]*py + R[8]*pz + t2;
        float ns  = sx*sx + sy*sy + sz*sz;
        float nt2 = tix*tix + tiy*tiy + tiz*tiz;
        float dp  = sx*tix + sy*tiy + sz*tiz;
        v1 = fmaxf(ns + nt2 - 2.f*dp, 0.f);

        float an = sqrtf(tnx*tnx + tny*tny + tnz*tnz);
        float nx = sn[3*jc+0], ny = sn[3*jc+1], nz = sn[3*jc+2];
        float wx = R[0]*nx + R[1]*ny + R[2]*nz;
        float wy = R[3]*nx + R[4]*ny + R[5]*nz;
        float wz = R[6]*nx + R[7]*ny + R[8]*nz;
        float wn = sqrtf(wx*wx + wy*wy + wz*wz);
        float cs = (tnx*wx + tny*wy + tnz*wz) /
                   (fmaxf(an, EPS) * fmaxf(wn, EPS));
        v3 = 1.f - fabsf(cs);
    }

    // deterministic block reduction (4 warps)
    float v[4] = {v0, v1, v2, v3};
#pragma unroll
    for (int k = 0; k < 4; k++)
#pragma unroll
        for (int off = 16; off; off >>= 1)
            v[k] += __shfl_xor_sync(0xFFFFFFFFu, v[k], off);

    __shared__ float sh[4][4];
    __shared__ bool s_last;
    const int warp = tid >> 5;
    if ((tid & 31) == 0) {
        sh[warp][0] = v[0]; sh[warp][1] = v[1];
        sh[warp][2] = v[2]; sh[warp][3] = v[3];
    }
    __syncthreads();
    if (tid == 0) {
#pragma unroll
        for (int k = 0; k < 4; k++) {
            float p = 0.f;
#pragma unroll
            for (int w = 0; w < 4; w++) p += sh[w][k];
            g_part[blockIdx.x][k] = p;
        }
        __threadfence();
        s_last = (atomicAdd(&g_done, 1u) == (unsigned)(FB - 1));
    }
    __syncthreads();

    if (s_last && tid < 32) {
        __threadfence();
        float w[4];
#pragma unroll
        for (int k = 0; k < 4; k++)
            w[k] = g_part[tid][k] + g_part[tid + 32][k];
#pragma unroll
        for (int k = 0; k < 4; k++)
#pragma unroll
            for (int off = 16; off; off >>= 1)
                w[k] += __shfl_xor_sync(0xFFFFFFFFu, w[k], off);
        if (tid == 0) {
            const float invN = 1.0f / (float)N_PTS;
            out[0] = w[0]*invN + w[1]*invN + 0.1f*(w[2]*invN + w[3]*invN);
            g_done = 0u;   // reset for next replay
        }
    }
}

// ---------------------------------------------------------------------------
extern "C" void kernel_launch(void* const* d_in, const int* in_sizes, int n_in,
                              void* d_out, int out_size) {
    const float* sp = (const float*)d_in[0];
    const float* tp = (const float*)d_in[1];
    const float* sn = (const float*)d_in[2];
    const float* tn = (const float*)d_in[3];
    const float* tr = (const float*)d_in[4];
    const float* r6 = (const float*)d_in[5];
    const float* sc = (const float*)d_in[6];
    float* out = (float*)d_out;

    k_pairs<<<NBLK, BT>>>(sp, tp, tr, r6, sc);

    // PDL launch of the epilogue: overlaps its prologue with k_pairs tail
    cudaLaunchConfig_t cfg = {};
    cfg.gridDim = dim3(FB);
    cfg.blockDim = dim3(FT);
    cfg.dynamicSmemBytes = 0;
    cfg.stream = 0;
    cudaLaunchAttribute attrs[1];
    attrs[0].id = cudaLaunchAttributeProgrammaticStreamSerialization;
    attrs[0].val.programmaticStreamSerializationAllowed = 1;
    cfg.attrs = attrs;
    cfg.numAttrs = 1;
    cudaLaunchKernelEx(&cfg, k_final, sp, tp, sn, tn, tr, r6, sc, (float*)out);
}